// round 5
// baseline (speedup 1.0000x reference)
#include <cuda_runtime.h>
#include <cstdint>

#define N_NODES  50000
#define N_EDGES  800000
#define N_GRAPHS 256
#define D_FEAT   96
#define HIDDEN   32

#define NB_SCAN  ((N_NODES + 255) / 256)   // 196
#define XT_STRIDE 68                        // 64 nodes + 4 pad
#define HS_STRIDE 36                        // 32 + 4 pad

// Scratch (no cudaMalloc allowed)
__device__ float g_y[N_NODES * HIDDEN];      // x @ W1
__device__ float g_pool[N_GRAPHS * HIDDEN];  // per-graph sums
__device__ float g_cnt[N_GRAPHS];            // per-graph node counts
__device__ unsigned g_done;                  // completion counter
__device__ int g_deg[N_NODES];               // in-degree
__device__ int g_rowstart[N_NODES];          // CSR row starts
__device__ int g_cursor[N_NODES];            // scatter cursors
__device__ int g_srcs[N_EDGES];              // CSR src ids (grouped by dst)
__device__ int g_bsum[NB_SCAN];              // scan block sums
__device__ int g_boff[NB_SCAN];              // scan block offsets

// ---------------- f32x2 helpers ----------------
__device__ __forceinline__ unsigned long long pk2(float lo, float hi) {
    unsigned long long r;
    asm("mov.b64 %0, {%1, %2};" : "=l"(r) : "f"(lo), "f"(hi));
    return r;
}
__device__ __forceinline__ void ffma2(unsigned long long& acc,
                                      unsigned long long a, unsigned long long b) {
    asm("fma.rn.f32x2 %0, %1, %2, %0;" : "+l"(acc) : "l"(a), "l"(b));
}
__device__ __forceinline__ float2 up2(unsigned long long v) {
    float2 r;
    asm("mov.b64 {%0, %1}, %2;" : "=f"(r.x), "=f"(r.y) : "l"(v));
    return r;
}

// ---------------------------------------------------------------------------
// k0: zero deg / pool / cnt / done
// ---------------------------------------------------------------------------
__global__ __launch_bounds__(256) void k0_zero() {
    const int i = blockIdx.x * 256 + threadIdx.x;
    if (i < N_NODES) g_deg[i] = 0;
    if (i < N_GRAPHS * HIDDEN) g_pool[i] = 0.0f;
    if (i < N_GRAPHS) g_cnt[i] = 0.0f;
    if (i == 0) g_done = 0u;
}

// ---------------------------------------------------------------------------
// kh: histogram of dst (int4-vectorized)
// ---------------------------------------------------------------------------
__global__ __launch_bounds__(256) void kh_hist(const int* __restrict__ ei) {
    const int t = blockIdx.x * 256 + threadIdx.x;
    if (t >= N_EDGES / 4) return;
    const int4 d4 = ((const int4*)(ei + N_EDGES))[t];
    atomicAdd(&g_deg[d4.x], 1);
    atomicAdd(&g_deg[d4.y], 1);
    atomicAdd(&g_deg[d4.z], 1);
    atomicAdd(&g_deg[d4.w], 1);
}

// ---------------------------------------------------------------------------
// kb1: per-block sums of deg
// ---------------------------------------------------------------------------
__global__ __launch_bounds__(256) void kb1_blocksum() {
    __shared__ int sh[256];
    const int t = threadIdx.x;
    const int i = blockIdx.x * 256 + t;
    sh[t] = (i < N_NODES) ? g_deg[i] : 0;
    __syncthreads();
    for (int off = 128; off > 0; off >>= 1) {
        if (t < off) sh[t] += sh[t + off];
        __syncthreads();
    }
    if (t == 0) g_bsum[blockIdx.x] = sh[0];
}

// ---------------------------------------------------------------------------
// kb2: exclusive scan over block sums (tiny, serial)
// ---------------------------------------------------------------------------
__global__ void kb2_scanblocks() {
    int acc = 0;
    for (int b = 0; b < NB_SCAN; b++) {
        g_boff[b] = acc;
        acc += g_bsum[b];
    }
}

// ---------------------------------------------------------------------------
// kb3: in-block exclusive scan + offset -> rowstart & cursor
// ---------------------------------------------------------------------------
__global__ __launch_bounds__(256) void kb3_rowstart() {
    __shared__ int sh[256];
    const int t = threadIdx.x;
    const int i = blockIdx.x * 256 + t;
    const int d = (i < N_NODES) ? g_deg[i] : 0;
    sh[t] = d;
    __syncthreads();
    for (int off = 1; off < 256; off <<= 1) {
        int v = (t >= off) ? sh[t - off] : 0;
        __syncthreads();
        sh[t] += v;
        __syncthreads();
    }
    if (i < N_NODES) {
        const int rs = g_boff[blockIdx.x] + sh[t] - d;  // exclusive
        g_rowstart[i] = rs;
        g_cursor[i]   = rs;
    }
}

// ---------------------------------------------------------------------------
// kc: scatter src ids into CSR slots
// ---------------------------------------------------------------------------
__global__ __launch_bounds__(256) void kc_scatter(const int* __restrict__ ei) {
    const int t = blockIdx.x * 256 + threadIdx.x;
    if (t >= N_EDGES / 4) return;
    const int4 s4 = ((const int4*)ei)[t];
    const int4 d4 = ((const int4*)(ei + N_EDGES))[t];
    g_srcs[atomicAdd(&g_cursor[d4.x], 1)] = s4.x;
    g_srcs[atomicAdd(&g_cursor[d4.y], 1)] = s4.y;
    g_srcs[atomicAdd(&g_cursor[d4.z], 1)] = s4.z;
    g_srcs[atomicAdd(&g_cursor[d4.w], 1)] = s4.w;
}

// ---------------------------------------------------------------------------
// k1: y = x @ W1. 64 nodes/block, 128 threads, 4 nodes x 4 cols per thread,
//     transposed x in smem, packed f32x2 FMAs.
// ---------------------------------------------------------------------------
__global__ __launch_bounds__(128) void k1_gemm_y(
    const float* __restrict__ x, const float* __restrict__ W1)
{
    __shared__ float W1s[D_FEAT * HIDDEN];        // 12 KB, row f contiguous
    __shared__ float xsT[D_FEAT * XT_STRIDE];     // 25.5 KB, xsT[f][node]

    const int tid = threadIdx.x;
    const int node0 = blockIdx.x * 64;

    // stage W1 (768 float4, coalesced)
    {
        const float4* W14 = (const float4*)W1;
        float4* W1s4 = (float4*)W1s;
        for (int i = tid; i < D_FEAT * HIDDEN / 4; i += 128)
            W1s4[i] = W14[i];
    }
    // stage x transposed: read float4 along feat (coalesced), write 4 rows
    {
        const float4* x4 = (const float4*)x;
        for (int i = tid; i < 64 * 24; i += 128) {   // 24 f-quads per node
            const int nl = i / 24, fq = i % 24;
            const int node = node0 + nl;
            float4 v = make_float4(0.f, 0.f, 0.f, 0.f);
            if (node < N_NODES) v = x4[node * 24 + fq];
            xsT[(fq * 4 + 0) * XT_STRIDE + nl] = v.x;
            xsT[(fq * 4 + 1) * XT_STRIDE + nl] = v.y;
            xsT[(fq * 4 + 2) * XT_STRIDE + nl] = v.z;
            xsT[(fq * 4 + 3) * XT_STRIDE + nl] = v.w;
        }
    }
    __syncthreads();

    const int nq = tid >> 3;   // 0..15 : node quad
    const int cq = tid & 7;    // 0..7  : col quad

    unsigned long long a01[4], a23[4];
#pragma unroll
    for (int c = 0; c < 4; c++) { a01[c] = 0ull; a23[c] = 0ull; }

#pragma unroll 4
    for (int f = 0; f < D_FEAT; f++) {
        const float4 xv = *(const float4*)&xsT[f * XT_STRIDE + nq * 4];
        const float4 wv = *(const float4*)&W1s[f * HIDDEN + cq * 4];
        const unsigned long long x01 = pk2(xv.x, xv.y);
        const unsigned long long x23 = pk2(xv.z, xv.w);
        unsigned long long w;
        w = pk2(wv.x, wv.x); ffma2(a01[0], x01, w); ffma2(a23[0], x23, w);
        w = pk2(wv.y, wv.y); ffma2(a01[1], x01, w); ffma2(a23[1], x23, w);
        w = pk2(wv.z, wv.z); ffma2(a01[2], x01, w); ffma2(a23[2], x23, w);
        w = pk2(wv.w, wv.w); ffma2(a01[3], x01, w); ffma2(a23[3], x23, w);
    }

    // unpack: node k, col c
    float2 u01[4], u23[4];
#pragma unroll
    for (int c = 0; c < 4; c++) { u01[c] = up2(a01[c]); u23[c] = up2(a23[c]); }

    const int nbase = node0 + nq * 4;
    if (nbase + 0 < N_NODES)
        *(float4*)&g_y[(nbase + 0) * HIDDEN + cq * 4] =
            make_float4(u01[0].x, u01[1].x, u01[2].x, u01[3].x);
    if (nbase + 1 < N_NODES)
        *(float4*)&g_y[(nbase + 1) * HIDDEN + cq * 4] =
            make_float4(u01[0].y, u01[1].y, u01[2].y, u01[3].y);
    if (nbase + 2 < N_NODES)
        *(float4*)&g_y[(nbase + 2) * HIDDEN + cq * 4] =
            make_float4(u23[0].x, u23[1].x, u23[2].x, u23[3].x);
    if (nbase + 3 < N_NODES)
        *(float4*)&g_y[(nbase + 3) * HIDDEN + cq * 4] =
            make_float4(u23[0].y, u23[1].y, u23[2].y, u23[3].y);
}

// ---------------------------------------------------------------------------
// k3: fused gather-reduce + MLP + pool + head epilogue.
//     Phase 1: warp per node (lane = column): acc = y[node] + sum y[src].
//     Phase 2: h2 = relu(h @ W2 + b2) float4-tiled; vector-RED into pool.
// ---------------------------------------------------------------------------
__global__ __launch_bounds__(256) void k3_fused(
    const float* __restrict__ b1, const float* __restrict__ W2,
    const float* __restrict__ b2, const int* __restrict__ batch,
    const float* __restrict__ Wc, const float* __restrict__ bc,
    float* __restrict__ out)
{
    __shared__ float W2s[HIDDEN * HIDDEN];   // 4 KB
    __shared__ float hs[32 * HS_STRIDE];     // 4.6 KB
    __shared__ bool amLast;

    const int tid  = threadIdx.x;
    const int lane = tid & 31;
    const int wid  = tid >> 5;
    const int node0 = blockIdx.x * 32;

    {
        const float4* W24 = (const float4*)W2;
        float4* W2s4 = (float4*)W2s;
        for (int i = tid; i < HIDDEN * HIDDEN / 4; i += 256)
            W2s4[i] = W24[i];
    }

    const float b1v = b1[lane];

    // -------- phase 1: gather-reduce, 4 nodes per warp --------
#pragma unroll
    for (int k = 0; k < 4; k++) {
        const int ln   = wid * 4 + k;        // local node 0..31
        const int node = node0 + ln;
        float acc = 0.0f;
        if (node < N_NODES) {
            acc = g_y[node * HIDDEN + lane];
            const int rs = g_rowstart[node];
            const int dg = g_deg[node];
            for (int j = 0; j < dg; j += 32) {
                const int cnt = min(32, dg - j);
                const int sid = (j + lane < dg) ? __ldg(&g_srcs[rs + j + lane]) : 0;
                for (int t = 0; t < cnt; t++) {
                    const int s = __shfl_sync(0xffffffffu, sid, t);
                    acc += g_y[s * HIDDEN + lane];
                }
            }
            acc = fmaxf(acc + b1v, 0.0f);
        }
        hs[ln * HS_STRIDE + lane] = acc;
    }
    __syncthreads();

    // -------- phase 2: h2 = relu(h @ W2 + b2), pool --------
    const int nl   = tid >> 3;
    const int sub  = tid & 7;
    const int node = node0 + nl;

    float4 acc = make_float4(0.f, 0.f, 0.f, 0.f);
#pragma unroll
    for (int kq = 0; kq < 8; kq++) {
        const float4 hv = *(const float4*)&hs[nl * HS_STRIDE + kq * 4];
        {
            const float4 wv = *(const float4*)&W2s[(kq * 4 + 0) * HIDDEN + sub * 4];
            acc.x += hv.x * wv.x; acc.y += hv.x * wv.y; acc.z += hv.x * wv.z; acc.w += hv.x * wv.w;
        }
        {
            const float4 wv = *(const float4*)&W2s[(kq * 4 + 1) * HIDDEN + sub * 4];
            acc.x += hv.y * wv.x; acc.y += hv.y * wv.y; acc.z += hv.y * wv.z; acc.w += hv.y * wv.w;
        }
        {
            const float4 wv = *(const float4*)&W2s[(kq * 4 + 2) * HIDDEN + sub * 4];
            acc.x += hv.z * wv.x; acc.y += hv.z * wv.y; acc.z += hv.z * wv.z; acc.w += hv.z * wv.w;
        }
        {
            const float4 wv = *(const float4*)&W2s[(kq * 4 + 3) * HIDDEN + sub * 4];
            acc.x += hv.w * wv.x; acc.y += hv.w * wv.y; acc.z += hv.w * wv.z; acc.w += hv.w * wv.w;
        }
    }

    if (node < N_NODES) {
        const float4 bv = *(const float4*)&b2[sub * 4];
        acc.x = fmaxf(acc.x + bv.x, 0.f);
        acc.y = fmaxf(acc.y + bv.y, 0.f);
        acc.z = fmaxf(acc.z + bv.z, 0.f);
        acc.w = fmaxf(acc.w + bv.w, 0.f);

        const int g = batch[node];
        float* p = &g_pool[g * HIDDEN + sub * 4];
        asm volatile("red.global.add.v4.f32 [%0], {%1, %2, %3, %4};"
                     :: "l"(p), "f"(acc.x), "f"(acc.y), "f"(acc.z), "f"(acc.w)
                     : "memory");
        if (sub == 0) atomicAdd(&g_cnt[g], 1.0f);
    }

    // -------- last-block epilogue (head GEMV) --------
    __threadfence();
    __syncthreads();
    if (tid == 0)
        amLast = (atomicAdd(&g_done, 1u) == gridDim.x - 1u);
    __syncthreads();

    if (amLast) {
        __threadfence();
        const int g = tid; // 256 threads = 256 graphs
        const float inv = 1.0f / fmaxf(g_cnt[g], 1.0f);
        float o0 = 0.0f, o1 = 0.0f;
#pragma unroll
        for (int k = 0; k < HIDDEN; k++) {
            const float p = g_pool[g * HIDDEN + k] * inv;
            o0 += p * Wc[k * 2 + 0];
            o1 += p * Wc[k * 2 + 1];
        }
        out[g * 2 + 0] = o0 + bc[0];
        out[g * 2 + 1] = o1 + bc[1];
    }
}

// ---------------------------------------------------------------------------
// launch — inputs: x, edge_index, batch, W1, b1, W2, b2, Wc, bc (idx int32)
// ---------------------------------------------------------------------------
extern "C" void kernel_launch(void* const* d_in, const int* in_sizes, int n_in,
                              void* d_out, int out_size)
{
    const float* x    = (const float*)d_in[0];
    const int*   ei   = (const int*)d_in[1];
    const int*   bat  = (const int*)d_in[2];
    const float* W1   = (const float*)d_in[3];
    const float* b1   = (const float*)d_in[4];
    const float* W2   = (const float*)d_in[5];
    const float* b2   = (const float*)d_in[6];
    const float* Wc   = (const float*)d_in[7];
    const float* bc   = (const float*)d_in[8];
    float*       out  = (float*)d_out;

    k0_zero<<<(N_NODES + 255) / 256, 256>>>();
    k1_gemm_y<<<(N_NODES + 63) / 64, 128>>>(x, W1);
    kh_hist<<<(N_EDGES / 4 + 255) / 256, 256>>>(ei);
    kb1_blocksum<<<NB_SCAN, 256>>>();
    kb2_scanblocks<<<1, 1>>>();
    kb3_rowstart<<<NB_SCAN, 256>>>();
    kc_scatter<<<(N_EDGES / 4 + 255) / 256, 256>>>(ei);
    k3_fused<<<(N_NODES + 31) / 32, 256>>>(b1, W2, b2, bat, Wc, bc, out);
}

// round 6
// speedup vs baseline: 1.4189x; 1.4189x over previous
#include <cuda_runtime.h>
#include <cstdint>

#define N_NODES  50000
#define N_EDGES  800000
#define N_GRAPHS 256
#define D_FEAT   96
#define HIDDEN   32

#define XT_STRIDE 68    // 64 nodes + 4 pad
#define HS_STRIDE 36    // 32 + 4 pad

// Scratch (no cudaMalloc allowed)
__device__ float g_y[N_NODES * HIDDEN];     // x @ W1
__device__ float g_agg[N_NODES * HIDDEN];   // scatter-add accumulator
__device__ float g_pool[N_GRAPHS * HIDDEN]; // per-graph sums
__device__ float g_cnt[N_GRAPHS];           // per-graph node counts
__device__ unsigned g_done;                 // k3 completion counter

// ---------------- f32x2 helpers ----------------
__device__ __forceinline__ unsigned long long pk2(float lo, float hi) {
    unsigned long long r;
    asm("mov.b64 %0, {%1, %2};" : "=l"(r) : "f"(lo), "f"(hi));
    return r;
}
__device__ __forceinline__ void ffma2(unsigned long long& acc,
                                      unsigned long long a, unsigned long long b) {
    asm("fma.rn.f32x2 %0, %1, %2, %0;" : "+l"(acc) : "l"(a), "l"(b));
}
__device__ __forceinline__ float2 up2(unsigned long long v) {
    float2 r;
    asm("mov.b64 {%0, %1}, %2;" : "=f"(r.x), "=f"(r.y) : "l"(v));
    return r;
}

// ---------------------------------------------------------------------------
// k1: y = x @ W1 (bias folded into k3). 64 nodes/block, 128 threads,
//     4 nodes x 4 cols per thread, transposed x in smem, f32x2 FMAs.
//     Also zeroes g_agg; block 0 zeroes pool/cnt/done.
// ---------------------------------------------------------------------------
__global__ __launch_bounds__(128) void k1_gemm_y(
    const float* __restrict__ x, const float* __restrict__ W1)
{
    __shared__ float W1s[D_FEAT * HIDDEN];        // 12 KB, row f contiguous
    __shared__ float xsT[D_FEAT * XT_STRIDE];     // 25.5 KB, xsT[f][node]

    const int tid = threadIdx.x;
    const int node0 = blockIdx.x * 64;

    // stage W1 (768 float4, coalesced)
    {
        const float4* W14 = (const float4*)W1;
        float4* W1s4 = (float4*)W1s;
        for (int i = tid; i < D_FEAT * HIDDEN / 4; i += 128)
            W1s4[i] = W14[i];
    }
    // stage x transposed: read float4 along feat (coalesced), write 4 rows
    {
        const float4* x4 = (const float4*)x;
        for (int i = tid; i < 64 * 24; i += 128) {   // 24 f-quads per node
            const int nl = i / 24, fq = i % 24;
            const int node = node0 + nl;
            float4 v = make_float4(0.f, 0.f, 0.f, 0.f);
            if (node < N_NODES) v = x4[node * 24 + fq];
            xsT[(fq * 4 + 0) * XT_STRIDE + nl] = v.x;
            xsT[(fq * 4 + 1) * XT_STRIDE + nl] = v.y;
            xsT[(fq * 4 + 2) * XT_STRIDE + nl] = v.z;
            xsT[(fq * 4 + 3) * XT_STRIDE + nl] = v.w;
        }
    }
    if (blockIdx.x == 0) {
        for (int i = tid; i < N_GRAPHS * HIDDEN; i += 128) g_pool[i] = 0.0f;
        for (int i = tid; i < N_GRAPHS; i += 128) g_cnt[i] = 0.0f;
        if (tid == 0) g_done = 0u;
    }
    __syncthreads();

    const int nq = tid >> 3;   // 0..15 : node quad
    const int cq = tid & 7;    // 0..7  : col quad

    unsigned long long a01[4], a23[4];
#pragma unroll
    for (int c = 0; c < 4; c++) { a01[c] = 0ull; a23[c] = 0ull; }

#pragma unroll 4
    for (int f = 0; f < D_FEAT; f++) {
        const float4 xv = *(const float4*)&xsT[f * XT_STRIDE + nq * 4];
        const float4 wv = *(const float4*)&W1s[f * HIDDEN + cq * 4];
        const unsigned long long x01 = pk2(xv.x, xv.y);
        const unsigned long long x23 = pk2(xv.z, xv.w);
        unsigned long long w;
        w = pk2(wv.x, wv.x); ffma2(a01[0], x01, w); ffma2(a23[0], x23, w);
        w = pk2(wv.y, wv.y); ffma2(a01[1], x01, w); ffma2(a23[1], x23, w);
        w = pk2(wv.z, wv.z); ffma2(a01[2], x01, w); ffma2(a23[2], x23, w);
        w = pk2(wv.w, wv.w); ffma2(a01[3], x01, w); ffma2(a23[3], x23, w);
    }

    float2 u01[4], u23[4];
#pragma unroll
    for (int c = 0; c < 4; c++) { u01[c] = up2(a01[c]); u23[c] = up2(a23[c]); }

    const float4 z4 = make_float4(0.f, 0.f, 0.f, 0.f);
    const int nbase = node0 + nq * 4;
    if (nbase + 0 < N_NODES) {
        *(float4*)&g_y[(nbase + 0) * HIDDEN + cq * 4] =
            make_float4(u01[0].x, u01[1].x, u01[2].x, u01[3].x);
        *(float4*)&g_agg[(nbase + 0) * HIDDEN + cq * 4] = z4;
    }
    if (nbase + 1 < N_NODES) {
        *(float4*)&g_y[(nbase + 1) * HIDDEN + cq * 4] =
            make_float4(u01[0].y, u01[1].y, u01[2].y, u01[3].y);
        *(float4*)&g_agg[(nbase + 1) * HIDDEN + cq * 4] = z4;
    }
    if (nbase + 2 < N_NODES) {
        *(float4*)&g_y[(nbase + 2) * HIDDEN + cq * 4] =
            make_float4(u23[0].x, u23[1].x, u23[2].x, u23[3].x);
        *(float4*)&g_agg[(nbase + 2) * HIDDEN + cq * 4] = z4;
    }
    if (nbase + 3 < N_NODES) {
        *(float4*)&g_y[(nbase + 3) * HIDDEN + cq * 4] =
            make_float4(u23[0].y, u23[1].y, u23[2].y, u23[3].y);
        *(float4*)&g_agg[(nbase + 3) * HIDDEN + cq * 4] = z4;
    }
}

// ---------------------------------------------------------------------------
// k2: edge scatter in 32-dim space; 8 lanes/edge, red.global.add.v4.f32
// ---------------------------------------------------------------------------
__global__ __launch_bounds__(256) void k2_scatter(
    const int* __restrict__ edge_index)
{
    const int t   = blockIdx.x * 256 + threadIdx.x;
    const int e   = t >> 3;
    const int sub = t & 7;
    if (e >= N_EDGES) return;

    const int s = __ldg(&edge_index[e]);            // src
    const int d = __ldg(&edge_index[N_EDGES + e]);  // dst

    const float4 v = *reinterpret_cast<const float4*>(&g_y[s * HIDDEN + sub * 4]);
    float* p = &g_agg[d * HIDDEN + sub * 4];
    asm volatile("red.global.add.v4.f32 [%0], {%1, %2, %3, %4};"
                 :: "l"(p), "f"(v.x), "f"(v.y), "f"(v.z), "f"(v.w)
                 : "memory");
}

// ---------------------------------------------------------------------------
// k3: h = relu(agg+y+b1); h2 = relu(h@W2+b2); pool via vector RED.
//     float4 tiling; last-block epilogue does the head GEMV.
// ---------------------------------------------------------------------------
__global__ __launch_bounds__(256) void k3_mlp_pool(
    const float* __restrict__ b1, const float* __restrict__ W2,
    const float* __restrict__ b2, const int* __restrict__ batch,
    const float* __restrict__ Wc, const float* __restrict__ bc,
    float* __restrict__ out)
{
    __shared__ float W2s[HIDDEN * HIDDEN];   // 4 KB
    __shared__ float hs[32 * HS_STRIDE];     // 4.6 KB
    __shared__ bool amLast;

    const int tid = threadIdx.x;
    const int node0 = blockIdx.x * 32;

    {
        const float4* W24 = (const float4*)W2;
        float4* W2s4 = (float4*)W2s;
        for (int i = tid; i < HIDDEN * HIDDEN / 4; i += 256)
            W2s4[i] = W24[i];
    }

    const int nl   = tid >> 3;
    const int sub  = tid & 7;
    const int node = node0 + nl;

    // h = relu(agg + y + b1), staged to smem
    {
        float4 h = make_float4(0.f, 0.f, 0.f, 0.f);
        if (node < N_NODES) {
            const float4 a  = *(const float4*)&g_agg[node * HIDDEN + sub * 4];
            const float4 yv = *(const float4*)&g_y[node * HIDDEN + sub * 4];
            const float4 bv = *(const float4*)&b1[sub * 4];
            h.x = fmaxf(a.x + yv.x + bv.x, 0.f);
            h.y = fmaxf(a.y + yv.y + bv.y, 0.f);
            h.z = fmaxf(a.z + yv.z + bv.z, 0.f);
            h.w = fmaxf(a.w + yv.w + bv.w, 0.f);
        }
        *(float4*)&hs[nl * HS_STRIDE + sub * 4] = h;
    }
    __syncthreads();

    // h2 = relu(h @ W2 + b2)
    float4 acc = make_float4(0.f, 0.f, 0.f, 0.f);
#pragma unroll
    for (int kq = 0; kq < 8; kq++) {
        const float4 hv = *(const float4*)&hs[nl * HS_STRIDE + kq * 4];
        {
            const float4 wv = *(const float4*)&W2s[(kq * 4 + 0) * HIDDEN + sub * 4];
            acc.x += hv.x * wv.x; acc.y += hv.x * wv.y; acc.z += hv.x * wv.z; acc.w += hv.x * wv.w;
        }
        {
            const float4 wv = *(const float4*)&W2s[(kq * 4 + 1) * HIDDEN + sub * 4];
            acc.x += hv.y * wv.x; acc.y += hv.y * wv.y; acc.z += hv.y * wv.z; acc.w += hv.y * wv.w;
        }
        {
            const float4 wv = *(const float4*)&W2s[(kq * 4 + 2) * HIDDEN + sub * 4];
            acc.x += hv.z * wv.x; acc.y += hv.z * wv.y; acc.z += hv.z * wv.z; acc.w += hv.z * wv.w;
        }
        {
            const float4 wv = *(const float4*)&W2s[(kq * 4 + 3) * HIDDEN + sub * 4];
            acc.x += hv.w * wv.x; acc.y += hv.w * wv.y; acc.z += hv.w * wv.z; acc.w += hv.w * wv.w;
        }
    }

    if (node < N_NODES) {
        const float4 bv = *(const float4*)&b2[sub * 4];
        acc.x = fmaxf(acc.x + bv.x, 0.f);
        acc.y = fmaxf(acc.y + bv.y, 0.f);
        acc.z = fmaxf(acc.z + bv.z, 0.f);
        acc.w = fmaxf(acc.w + bv.w, 0.f);

        const int g = batch[node];
        float* p = &g_pool[g * HIDDEN + sub * 4];
        asm volatile("red.global.add.v4.f32 [%0], {%1, %2, %3, %4};"
                     :: "l"(p), "f"(acc.x), "f"(acc.y), "f"(acc.z), "f"(acc.w)
                     : "memory");
        if (sub == 0) atomicAdd(&g_cnt[g], 1.0f);
    }

    // -------- last-block epilogue (head GEMV) --------
    __threadfence();
    __syncthreads();
    if (tid == 0)
        amLast = (atomicAdd(&g_done, 1u) == gridDim.x - 1u);
    __syncthreads();

    if (amLast) {
        __threadfence();
        const int g = tid; // 256 threads = 256 graphs
        const float inv = 1.0f / fmaxf(g_cnt[g], 1.0f);
        float o0 = 0.0f, o1 = 0.0f;
#pragma unroll
        for (int k = 0; k < HIDDEN; k++) {
            const float p = g_pool[g * HIDDEN + k] * inv;
            o0 += p * Wc[k * 2 + 0];
            o1 += p * Wc[k * 2 + 1];
        }
        out[g * 2 + 0] = o0 + bc[0];
        out[g * 2 + 1] = o1 + bc[1];
    }
}

// ---------------------------------------------------------------------------
// launch — inputs: x, edge_index, batch, W1, b1, W2, b2, Wc, bc (idx int32)
// ---------------------------------------------------------------------------
extern "C" void kernel_launch(void* const* d_in, const int* in_sizes, int n_in,
                              void* d_out, int out_size)
{
    const float* x    = (const float*)d_in[0];
    const int*   ei   = (const int*)d_in[1];
    const int*   bat  = (const int*)d_in[2];
    const float* W1   = (const float*)d_in[3];
    const float* b1   = (const float*)d_in[4];
    const float* W2   = (const float*)d_in[5];
    const float* b2   = (const float*)d_in[6];
    const float* Wc   = (const float*)d_in[7];
    const float* bc   = (const float*)d_in[8];
    float*       out  = (float*)d_out;

    k1_gemm_y<<<(N_NODES + 63) / 64, 128>>>(x, W1);
    k2_scatter<<<(N_EDGES * 8 + 255) / 256, 256>>>(ei);
    k3_mlp_pool<<<(N_NODES + 31) / 32, 256>>>(b1, W2, b2, bat, Wc, bc, out);
}

// round 7
// speedup vs baseline: 1.6045x; 1.1308x over previous
#include <cuda_runtime.h>
#include <cstdint>

#define N_NODES  50000
#define N_EDGES  800000
#define N_GRAPHS 256
#define D_FEAT   96
#define HIDDEN   32

#define XT_STRIDE 66    // 64 nodes + 2 pad (even keeps 8B alignment for pair loads)
#define HS_STRIDE 36    // 32 + 4 pad

// Scratch (no cudaMalloc allowed)
__device__ float g_y[N_NODES * HIDDEN];     // x @ W1 (read by k2 gather)
__device__ float g_agg[N_NODES * HIDDEN];   // accumulator, initialized to y
__device__ float g_pool[N_GRAPHS * HIDDEN]; // per-graph sums
__device__ float g_cnt[N_GRAPHS];           // per-graph node counts
__device__ unsigned g_done;                 // k3 completion counter

// ---------------- f32x2 helpers ----------------
__device__ __forceinline__ unsigned long long pk2(float lo, float hi) {
    unsigned long long r;
    asm("mov.b64 %0, {%1, %2};" : "=l"(r) : "f"(lo), "f"(hi));
    return r;
}
__device__ __forceinline__ void ffma2(unsigned long long& acc,
                                      unsigned long long a, unsigned long long b) {
    asm("fma.rn.f32x2 %0, %1, %2, %0;" : "+l"(acc) : "l"(a), "l"(b));
}
__device__ __forceinline__ float2 up2(unsigned long long v) {
    float2 r;
    asm("mov.b64 {%0, %1}, %2;" : "=f"(r.x), "=f"(r.y) : "l"(v));
    return r;
}

// ---------------------------------------------------------------------------
// k1: y = x @ W1. 64 nodes/block, 256 threads, 2 nodes x 4 cols per thread.
//     Transposed x in smem (pair loads), W-quads as packed u64 pairs.
//     Writes g_y AND g_agg = y. Block 0 zeroes pool/cnt/done.
// ---------------------------------------------------------------------------
__global__ __launch_bounds__(256) void k1_gemm_y(
    const float* __restrict__ x, const float* __restrict__ W1)
{
    __shared__ float W1s[D_FEAT * HIDDEN];        // 12 KB
    __shared__ float xsT[D_FEAT * XT_STRIDE];     // 25.3 KB, xsT[f][node]

    const int tid = threadIdx.x;
    const int node0 = blockIdx.x * 64;

    // stage W1 (768 float4, coalesced)
    {
        const float4* W14 = (const float4*)W1;
        float4* W1s4 = (float4*)W1s;
        for (int i = tid; i < D_FEAT * HIDDEN / 4; i += 256)
            W1s4[i] = W14[i];
    }
    // stage x transposed: read float4 along feat (coalesced), write 4 rows
    {
        const float4* x4 = (const float4*)x;
        for (int i = tid; i < 64 * 24; i += 256) {   // 24 f-quads per node
            const int nl = i / 24, fq = i % 24;
            const int node = node0 + nl;
            float4 v = make_float4(0.f, 0.f, 0.f, 0.f);
            if (node < N_NODES) v = x4[node * 24 + fq];
            xsT[(fq * 4 + 0) * XT_STRIDE + nl] = v.x;
            xsT[(fq * 4 + 1) * XT_STRIDE + nl] = v.y;
            xsT[(fq * 4 + 2) * XT_STRIDE + nl] = v.z;
            xsT[(fq * 4 + 3) * XT_STRIDE + nl] = v.w;
        }
    }
    if (blockIdx.x == 0) {
        for (int i = tid; i < N_GRAPHS * HIDDEN; i += 256) g_pool[i] = 0.0f;
        if (tid < N_GRAPHS) g_cnt[tid] = 0.0f;
        if (tid == 0) g_done = 0u;
    }
    __syncthreads();

    const int np = tid >> 3;   // 0..31 : node pair
    const int cq = tid & 7;    // 0..7  : col quad

    // acc[n][p]: node n in {0,1}, col pair p in {cols cq*4+0/1, cq*4+2/3}
    unsigned long long a00 = 0ull, a01 = 0ull, a10 = 0ull, a11 = 0ull;

#pragma unroll 4
    for (int f = 0; f < D_FEAT; f++) {
        const float2 xv = *(const float2*)&xsT[f * XT_STRIDE + np * 2];
        const ulonglong2 w2 = *(const ulonglong2*)&W1s[f * HIDDEN + cq * 4];
        const unsigned long long xd0 = pk2(xv.x, xv.x);
        const unsigned long long xd1 = pk2(xv.y, xv.y);
        ffma2(a00, xd0, w2.x);
        ffma2(a01, xd0, w2.y);
        ffma2(a10, xd1, w2.x);
        ffma2(a11, xd1, w2.y);
    }

    const float2 u00 = up2(a00), u01 = up2(a01), u10 = up2(a10), u11 = up2(a11);
    const int n0 = node0 + np * 2;

    if (n0 < N_NODES) {
        const float4 r = make_float4(u00.x, u00.y, u01.x, u01.y);
        *(float4*)&g_y[n0 * HIDDEN + cq * 4]   = r;
        *(float4*)&g_agg[n0 * HIDDEN + cq * 4] = r;
    }
    if (n0 + 1 < N_NODES) {
        const float4 r = make_float4(u10.x, u10.y, u11.x, u11.y);
        *(float4*)&g_y[(n0 + 1) * HIDDEN + cq * 4]   = r;
        *(float4*)&g_agg[(n0 + 1) * HIDDEN + cq * 4] = r;
    }
}

// ---------------------------------------------------------------------------
// k2: edge scatter in 32-dim space; 8 lanes/edge, red.global.add.v4.f32
// ---------------------------------------------------------------------------
__global__ __launch_bounds__(256) void k2_scatter(
    const int* __restrict__ edge_index)
{
    const int t   = blockIdx.x * 256 + threadIdx.x;
    const int e   = t >> 3;
    const int sub = t & 7;
    if (e >= N_EDGES) return;

    const int s = __ldg(&edge_index[e]);            // src
    const int d = __ldg(&edge_index[N_EDGES + e]);  // dst

    const float4 v = *reinterpret_cast<const float4*>(&g_y[s * HIDDEN + sub * 4]);
    float* p = &g_agg[d * HIDDEN + sub * 4];
    asm volatile("red.global.add.v4.f32 [%0], {%1, %2, %3, %4};"
                 :: "l"(p), "f"(v.x), "f"(v.y), "f"(v.z), "f"(v.w)
                 : "memory");
}

// ---------------------------------------------------------------------------
// k3: h = relu(agg+b1) (agg already includes y); h2 = relu(h@W2+b2);
//     run-length smem pooling (batch is sorted) -> few vector REDs per block;
//     last-block epilogue does the head GEMV.
// ---------------------------------------------------------------------------
__global__ __launch_bounds__(256) void k3_mlp_pool(
    const float* __restrict__ b1, const float* __restrict__ W2,
    const float* __restrict__ b2, const int* __restrict__ batch,
    const float* __restrict__ Wc, const float* __restrict__ bc,
    float* __restrict__ out)
{
    __shared__ float W2s[HIDDEN * HIDDEN];   // 4 KB
    __shared__ float hs[32 * HS_STRIDE];     // 4.6 KB (layer-1 output)
    __shared__ float h2s[32 * HS_STRIDE];    // 4.6 KB (layer-2 output)
    __shared__ int   sb[32];                 // batch ids of this block's nodes
    __shared__ bool  amLast;

    const int tid = threadIdx.x;
    const int node0 = blockIdx.x * 32;

    {
        const float4* W24 = (const float4*)W2;
        float4* W2s4 = (float4*)W2s;
        for (int i = tid; i < HIDDEN * HIDDEN / 4; i += 256)
            W2s4[i] = W24[i];
    }
    if (tid < 32) {
        const int nd = node0 + tid;
        sb[tid] = (nd < N_NODES) ? batch[nd] : -1;
    }

    const int nl   = tid >> 3;
    const int sub  = tid & 7;
    const int node = node0 + nl;

    // h = relu(agg + b1), staged to smem
    {
        float4 h = make_float4(0.f, 0.f, 0.f, 0.f);
        if (node < N_NODES) {
            const float4 a  = *(const float4*)&g_agg[node * HIDDEN + sub * 4];
            const float4 bv = *(const float4*)&b1[sub * 4];
            h.x = fmaxf(a.x + bv.x, 0.f);
            h.y = fmaxf(a.y + bv.y, 0.f);
            h.z = fmaxf(a.z + bv.z, 0.f);
            h.w = fmaxf(a.w + bv.w, 0.f);
        }
        *(float4*)&hs[nl * HS_STRIDE + sub * 4] = h;
    }
    __syncthreads();

    // h2 = relu(h @ W2 + b2)
    float4 acc = make_float4(0.f, 0.f, 0.f, 0.f);
#pragma unroll
    for (int kq = 0; kq < 8; kq++) {
        const float4 hv = *(const float4*)&hs[nl * HS_STRIDE + kq * 4];
        {
            const float4 wv = *(const float4*)&W2s[(kq * 4 + 0) * HIDDEN + sub * 4];
            acc.x += hv.x * wv.x; acc.y += hv.x * wv.y; acc.z += hv.x * wv.z; acc.w += hv.x * wv.w;
        }
        {
            const float4 wv = *(const float4*)&W2s[(kq * 4 + 1) * HIDDEN + sub * 4];
            acc.x += hv.y * wv.x; acc.y += hv.y * wv.y; acc.z += hv.y * wv.z; acc.w += hv.y * wv.w;
        }
        {
            const float4 wv = *(const float4*)&W2s[(kq * 4 + 2) * HIDDEN + sub * 4];
            acc.x += hv.z * wv.x; acc.y += hv.z * wv.y; acc.z += hv.z * wv.z; acc.w += hv.z * wv.w;
        }
        {
            const float4 wv = *(const float4*)&W2s[(kq * 4 + 3) * HIDDEN + sub * 4];
            acc.x += hv.w * wv.x; acc.y += hv.w * wv.y; acc.z += hv.w * wv.z; acc.w += hv.w * wv.w;
        }
    }

    {
        const float4 bv = *(const float4*)&b2[sub * 4];
        acc.x = fmaxf(acc.x + bv.x, 0.f);
        acc.y = fmaxf(acc.y + bv.y, 0.f);
        acc.z = fmaxf(acc.z + bv.z, 0.f);
        acc.w = fmaxf(acc.w + bv.w, 0.f);
        *(float4*)&h2s[nl * HS_STRIDE + sub * 4] = acc;
    }
    __syncthreads();

    // run-length pooling: batch is sorted, so nodes form contiguous graph runs.
    // 8 threads (one per col-quad) scan the 32 nodes, one RED per run.
    if (tid < 8) {
        const int cq = tid;
        float4 pacc = make_float4(0.f, 0.f, 0.f, 0.f);
        float cnt = 0.0f;
        int curg = -1;
        for (int n = 0; n < 32; n++) {
            const int g = sb[n];
            if (g != curg) {
                if (curg >= 0) {
                    float* p = &g_pool[curg * HIDDEN + cq * 4];
                    asm volatile("red.global.add.v4.f32 [%0], {%1, %2, %3, %4};"
                                 :: "l"(p), "f"(pacc.x), "f"(pacc.y), "f"(pacc.z), "f"(pacc.w)
                                 : "memory");
                    if (cq == 0) atomicAdd(&g_cnt[curg], cnt);
                }
                curg = g;
                pacc = make_float4(0.f, 0.f, 0.f, 0.f);
                cnt = 0.0f;
            }
            if (g >= 0) {
                const float4 h = *(const float4*)&h2s[n * HS_STRIDE + cq * 4];
                pacc.x += h.x; pacc.y += h.y; pacc.z += h.z; pacc.w += h.w;
                cnt += 1.0f;
            }
        }
        if (curg >= 0) {
            float* p = &g_pool[curg * HIDDEN + cq * 4];
            asm volatile("red.global.add.v4.f32 [%0], {%1, %2, %3, %4};"
                         :: "l"(p), "f"(pacc.x), "f"(pacc.y), "f"(pacc.z), "f"(pacc.w)
                         : "memory");
            if (cq == 0) atomicAdd(&g_cnt[curg], cnt);
        }
    }

    // -------- last-block epilogue (head GEMV) --------
    __threadfence();
    __syncthreads();
    if (tid == 0)
        amLast = (atomicAdd(&g_done, 1u) == gridDim.x - 1u);
    __syncthreads();

    if (amLast) {
        __threadfence();
        const int g = tid; // 256 threads = 256 graphs
        const float inv = 1.0f / fmaxf(g_cnt[g], 1.0f);
        float o0 = 0.0f, o1 = 0.0f;
#pragma unroll
        for (int k = 0; k < HIDDEN; k++) {
            const float p = g_pool[g * HIDDEN + k] * inv;
            o0 += p * Wc[k * 2 + 0];
            o1 += p * Wc[k * 2 + 1];
        }
        out[g * 2 + 0] = o0 + bc[0];
        out[g * 2 + 1] = o1 + bc[1];
    }
}

// ---------------------------------------------------------------------------
// launch — inputs: x, edge_index, batch, W1, b1, W2, b2, Wc, bc (idx int32)
// ---------------------------------------------------------------------------
extern "C" void kernel_launch(void* const* d_in, const int* in_sizes, int n_in,
                              void* d_out, int out_size)
{
    const float* x    = (const float*)d_in[0];
    const int*   ei   = (const int*)d_in[1];
    const int*   bat  = (const int*)d_in[2];
    const float* W1   = (const float*)d_in[3];
    const float* b1   = (const float*)d_in[4];
    const float* W2   = (const float*)d_in[5];
    const float* b2   = (const float*)d_in[6];
    const float* Wc   = (const float*)d_in[7];
    const float* bc   = (const float*)d_in[8];
    float*       out  = (float*)d_out;

    k1_gemm_y<<<(N_NODES + 63) / 64, 256>>>(x, W1);
    k2_scatter<<<(N_EDGES * 8 + 255) / 256, 256>>>(ei);
    k3_mlp_pool<<<(N_NODES + 31) / 32, 256>>>(b1, W2, b2, bat, Wc, bc, out);
}

// round 8
// speedup vs baseline: 1.6159x; 1.0071x over previous
#include <cuda_runtime.h>
#include <cstdint>

#define N_NODES  50000
#define N_EDGES  800000
#define N_GRAPHS 256
#define D_FEAT   96
#define HIDDEN   32

#define F_HALF    48    // features per pass
#define XT_STRIDE 66    // 64 nodes + 2 pad (8B alignment for pair loads)
#define HS_STRIDE 36    // 32 + 4 pad

// Scratch (no cudaMalloc allowed)
__device__ float g_y[N_NODES * HIDDEN];     // x @ W1 (clean copy, k2 gather src)
__device__ float g_agg[N_NODES * HIDDEN];   // accumulator, initialized to y
__device__ float g_pool[N_GRAPHS * HIDDEN]; // per-graph sums
__device__ float g_cnt[N_GRAPHS];           // per-graph node counts
__device__ unsigned g_done;                 // k3 completion counter

// ---------------- f32x2 helpers ----------------
__device__ __forceinline__ unsigned long long pk2(float lo, float hi) {
    unsigned long long r;
    asm("mov.b64 %0, {%1, %2};" : "=l"(r) : "f"(lo), "f"(hi));
    return r;
}
__device__ __forceinline__ void ffma2(unsigned long long& acc,
                                      unsigned long long a, unsigned long long b) {
    asm("fma.rn.f32x2 %0, %1, %2, %0;" : "+l"(acc) : "l"(a), "l"(b));
}
__device__ __forceinline__ float2 up2(unsigned long long v) {
    float2 r;
    asm("mov.b64 {%0, %1}, %2;" : "=f"(r.x), "=f"(r.y) : "l"(v));
    return r;
}

// ---------------------------------------------------------------------------
// k1: y = x @ W1. 64 nodes/block, 256 threads, 2 nodes x 4 cols per thread.
//     TWO PASSES over f (48 each): halves xsT -> 24.7 KB smem -> 8 blocks/SM,
//     single wave at grid=782. Writes g_y AND g_agg = y.
// ---------------------------------------------------------------------------
__global__ __launch_bounds__(256) void k1_gemm_y(
    const float* __restrict__ x, const float* __restrict__ W1)
{
    __shared__ float W1s[D_FEAT * HIDDEN];        // 12 KB (all 96 rows)
    __shared__ float xsT[F_HALF * XT_STRIDE];     // 12.7 KB, xsT[f][node]

    const int tid = threadIdx.x;
    const int node0 = blockIdx.x * 64;

    // stage W1 once (768 float4, coalesced)
    {
        const float4* W14 = (const float4*)W1;
        float4* W1s4 = (float4*)W1s;
        for (int i = tid; i < D_FEAT * HIDDEN / 4; i += 256)
            W1s4[i] = W14[i];
    }
    if (blockIdx.x == 0) {
        for (int i = tid; i < N_GRAPHS * HIDDEN; i += 256) g_pool[i] = 0.0f;
        if (tid < N_GRAPHS) g_cnt[tid] = 0.0f;
        if (tid == 0) g_done = 0u;
    }

    const int np = tid >> 3;   // 0..31 : node pair
    const int cq = tid & 7;    // 0..7  : col quad

    unsigned long long a00 = 0ull, a01 = 0ull, a10 = 0ull, a11 = 0ull;

#pragma unroll
    for (int half = 0; half < 2; half++) {
        __syncthreads();   // protect xsT reuse (and W1s readiness on first pass)
        // stage x transposed for f in [half*48, half*48+48)
        {
            const float4* x4 = (const float4*)x;
            for (int i = tid; i < 64 * 12; i += 256) {   // 12 f-quads per node
                const int nl = i / 12, fq = i % 12;
                const int node = node0 + nl;
                float4 v = make_float4(0.f, 0.f, 0.f, 0.f);
                if (node < N_NODES) v = x4[node * 24 + half * 12 + fq];
                xsT[(fq * 4 + 0) * XT_STRIDE + nl] = v.x;
                xsT[(fq * 4 + 1) * XT_STRIDE + nl] = v.y;
                xsT[(fq * 4 + 2) * XT_STRIDE + nl] = v.z;
                xsT[(fq * 4 + 3) * XT_STRIDE + nl] = v.w;
            }
        }
        __syncthreads();

        const float* W1h = &W1s[half * F_HALF * HIDDEN];
#pragma unroll 4
        for (int f = 0; f < F_HALF; f++) {
            const float2 xv = *(const float2*)&xsT[f * XT_STRIDE + np * 2];
            const ulonglong2 w2 = *(const ulonglong2*)&W1h[f * HIDDEN + cq * 4];
            const unsigned long long xd0 = pk2(xv.x, xv.x);
            const unsigned long long xd1 = pk2(xv.y, xv.y);
            ffma2(a00, xd0, w2.x);
            ffma2(a01, xd0, w2.y);
            ffma2(a10, xd1, w2.x);
            ffma2(a11, xd1, w2.y);
        }
    }

    const float2 u00 = up2(a00), u01 = up2(a01), u10 = up2(a10), u11 = up2(a11);
    const int n0 = node0 + np * 2;

    if (n0 < N_NODES) {
        const float4 r = make_float4(u00.x, u00.y, u01.x, u01.y);
        *(float4*)&g_y[n0 * HIDDEN + cq * 4]   = r;
        *(float4*)&g_agg[n0 * HIDDEN + cq * 4] = r;
    }
    if (n0 + 1 < N_NODES) {
        const float4 r = make_float4(u10.x, u10.y, u11.x, u11.y);
        *(float4*)&g_y[(n0 + 1) * HIDDEN + cq * 4]   = r;
        *(float4*)&g_agg[(n0 + 1) * HIDDEN + cq * 4] = r;
    }
}

// ---------------------------------------------------------------------------
// k2: edge scatter in 32-dim space; 8 lanes/edge, red.global.add.v4.f32
// ---------------------------------------------------------------------------
__global__ __launch_bounds__(256) void k2_scatter(
    const int* __restrict__ edge_index)
{
    const int t   = blockIdx.x * 256 + threadIdx.x;
    const int e   = t >> 3;
    const int sub = t & 7;
    if (e >= N_EDGES) return;

    const int s = __ldg(&edge_index[e]);            // src
    const int d = __ldg(&edge_index[N_EDGES + e]);  // dst

    const float4 v = *reinterpret_cast<const float4*>(&g_y[s * HIDDEN + sub * 4]);
    float* p = &g_agg[d * HIDDEN + sub * 4];
    asm volatile("red.global.add.v4.f32 [%0], {%1, %2, %3, %4};"
                 :: "l"(p), "f"(v.x), "f"(v.y), "f"(v.z), "f"(v.w)
                 : "memory");
}

// ---------------------------------------------------------------------------
// k3: h = relu(agg+b1) (agg already includes y); h2 = relu(h@W2+b2);
//     run-length smem pooling (batch is sorted); last-block head epilogue.
// ---------------------------------------------------------------------------
__global__ __launch_bounds__(256) void k3_mlp_pool(
    const float* __restrict__ b1, const float* __restrict__ W2,
    const float* __restrict__ b2, const int* __restrict__ batch,
    const float* __restrict__ Wc, const float* __restrict__ bc,
    float* __restrict__ out)
{
    __shared__ float W2s[HIDDEN * HIDDEN];   // 4 KB
    __shared__ float hs[32 * HS_STRIDE];     // 4.6 KB (layer-1 output)
    __shared__ float h2s[32 * HS_STRIDE];    // 4.6 KB (layer-2 output)
    __shared__ int   sb[32];                 // batch ids of this block's nodes
    __shared__ bool  amLast;

    const int tid = threadIdx.x;
    const int node0 = blockIdx.x * 32;

    {
        const float4* W24 = (const float4*)W2;
        float4* W2s4 = (float4*)W2s;
        for (int i = tid; i < HIDDEN * HIDDEN / 4; i += 256)
            W2s4[i] = W24[i];
    }
    if (tid < 32) {
        const int nd = node0 + tid;
        sb[tid] = (nd < N_NODES) ? batch[nd] : -1;
    }

    const int nl   = tid >> 3;
    const int sub  = tid & 7;
    const int node = node0 + nl;

    // h = relu(agg + b1), staged to smem
    {
        float4 h = make_float4(0.f, 0.f, 0.f, 0.f);
        if (node < N_NODES) {
            const float4 a  = *(const float4*)&g_agg[node * HIDDEN + sub * 4];
            const float4 bv = *(const float4*)&b1[sub * 4];
            h.x = fmaxf(a.x + bv.x, 0.f);
            h.y = fmaxf(a.y + bv.y, 0.f);
            h.z = fmaxf(a.z + bv.z, 0.f);
            h.w = fmaxf(a.w + bv.w, 0.f);
        }
        *(float4*)&hs[nl * HS_STRIDE + sub * 4] = h;
    }
    __syncthreads();

    // h2 = relu(h @ W2 + b2)
    float4 acc = make_float4(0.f, 0.f, 0.f, 0.f);
#pragma unroll
    for (int kq = 0; kq < 8; kq++) {
        const float4 hv = *(const float4*)&hs[nl * HS_STRIDE + kq * 4];
        {
            const float4 wv = *(const float4*)&W2s[(kq * 4 + 0) * HIDDEN + sub * 4];
            acc.x += hv.x * wv.x; acc.y += hv.x * wv.y; acc.z += hv.x * wv.z; acc.w += hv.x * wv.w;
        }
        {
            const float4 wv = *(const float4*)&W2s[(kq * 4 + 1) * HIDDEN + sub * 4];
            acc.x += hv.y * wv.x; acc.y += hv.y * wv.y; acc.z += hv.y * wv.z; acc.w += hv.y * wv.w;
        }
        {
            const float4 wv = *(const float4*)&W2s[(kq * 4 + 2) * HIDDEN + sub * 4];
            acc.x += hv.z * wv.x; acc.y += hv.z * wv.y; acc.z += hv.z * wv.z; acc.w += hv.z * wv.w;
        }
        {
            const float4 wv = *(const float4*)&W2s[(kq * 4 + 3) * HIDDEN + sub * 4];
            acc.x += hv.w * wv.x; acc.y += hv.w * wv.y; acc.z += hv.w * wv.z; acc.w += hv.w * wv.w;
        }
    }

    {
        const float4 bv = *(const float4*)&b2[sub * 4];
        acc.x = fmaxf(acc.x + bv.x, 0.f);
        acc.y = fmaxf(acc.y + bv.y, 0.f);
        acc.z = fmaxf(acc.z + bv.z, 0.f);
        acc.w = fmaxf(acc.w + bv.w, 0.f);
        *(float4*)&h2s[nl * HS_STRIDE + sub * 4] = acc;
    }
    __syncthreads();

    // run-length pooling: batch is sorted -> contiguous graph runs per block.
    if (tid < 8) {
        const int cq = tid;
        float4 pacc = make_float4(0.f, 0.f, 0.f, 0.f);
        float cnt = 0.0f;
        int curg = -1;
        for (int n = 0; n < 32; n++) {
            const int g = sb[n];
            if (g != curg) {
                if (curg >= 0) {
                    float* p = &g_pool[curg * HIDDEN + cq * 4];
                    asm volatile("red.global.add.v4.f32 [%0], {%1, %2, %3, %4};"
                                 :: "l"(p), "f"(pacc.x), "f"(pacc.y), "f"(pacc.z), "f"(pacc.w)
                                 : "memory");
                    if (cq == 0) atomicAdd(&g_cnt[curg], cnt);
                }
                curg = g;
                pacc = make_float4(0.f, 0.f, 0.f, 0.f);
                cnt = 0.0f;
            }
            if (g >= 0) {
                const float4 h = *(const float4*)&h2s[n * HS_STRIDE + cq * 4];
                pacc.x += h.x; pacc.y += h.y; pacc.z += h.z; pacc.w += h.w;
                cnt += 1.0f;
            }
        }
        if (curg >= 0) {
            float* p = &g_pool[curg * HIDDEN + cq * 4];
            asm volatile("red.global.add.v4.f32 [%0], {%1, %2, %3, %4};"
                         :: "l"(p), "f"(pacc.x), "f"(pacc.y), "f"(pacc.z), "f"(pacc.w)
                         : "memory");
            if (cq == 0) atomicAdd(&g_cnt[curg], cnt);
        }
    }

    // -------- last-block epilogue (head GEMV) --------
    __threadfence();
    __syncthreads();
    if (tid == 0)
        amLast = (atomicAdd(&g_done, 1u) == gridDim.x - 1u);
    __syncthreads();

    if (amLast) {
        __threadfence();
        const int g = tid; // 256 threads = 256 graphs
        const float inv = 1.0f / fmaxf(g_cnt[g], 1.0f);
        float o0 = 0.0f, o1 = 0.0f;
#pragma unroll
        for (int k = 0; k < HIDDEN; k++) {
            const float p = g_pool[g * HIDDEN + k] * inv;
            o0 += p * Wc[k * 2 + 0];
            o1 += p * Wc[k * 2 + 1];
        }
        out[g * 2 + 0] = o0 + bc[0];
        out[g * 2 + 1] = o1 + bc[1];
    }
}

// ---------------------------------------------------------------------------
// launch — inputs: x, edge_index, batch, W1, b1, W2, b2, Wc, bc (idx int32)
// ---------------------------------------------------------------------------
extern "C" void kernel_launch(void* const* d_in, const int* in_sizes, int n_in,
                              void* d_out, int out_size)
{
    const float* x    = (const float*)d_in[0];
    const int*   ei   = (const int*)d_in[1];
    const int*   bat  = (const int*)d_in[2];
    const float* W1   = (const float*)d_in[3];
    const float* b1   = (const float*)d_in[4];
    const float* W2   = (const float*)d_in[5];
    const float* b2   = (const float*)d_in[6];
    const float* Wc   = (const float*)d_in[7];
    const float* bc   = (const float*)d_in[8];
    float*       out  = (float*)d_out;

    k1_gemm_y<<<(N_NODES + 63) / 64, 256>>>(x, W1);
    k2_scatter<<<(N_EDGES * 8 + 255) / 256, 256>>>(ei);
    k3_mlp_pool<<<(N_NODES + 31) / 32, 256>>>(b1, W2, b2, bat, Wc, bc, out);
}

// round 9
// speedup vs baseline: 1.7099x; 1.0582x over previous
#include <cuda_runtime.h>
#include <cstdint>

#define N_NODES  50000
#define N_EDGES  800000
#define N_GRAPHS 256
#define D_FEAT   96
#define HIDDEN   32

#define XS_STRIDE 100   // 96 + 4 pad floats; node stride mod 32 banks = 4 -> 8 nodes distinct banks
#define HS_STRIDE 36    // 32 + 4 pad

// Scratch (no cudaMalloc allowed)
__device__ float g_y[N_NODES * HIDDEN];     // x @ W1 (clean copy, k2 gather src)
__device__ float g_agg[N_NODES * HIDDEN];   // accumulator, initialized to y
__device__ float g_pool[N_GRAPHS * HIDDEN]; // per-graph sums
__device__ float g_cnt[N_GRAPHS];           // per-graph node counts
__device__ unsigned g_done;                 // k3 completion counter

// ---------------- f32x2 helpers ----------------
__device__ __forceinline__ unsigned long long pk2(float lo, float hi) {
    unsigned long long r;
    asm("mov.b64 %0, {%1, %2};" : "=l"(r) : "f"(lo), "f"(hi));
    return r;
}
__device__ __forceinline__ void ffma2(unsigned long long& acc,
                                      unsigned long long a, unsigned long long b) {
    asm("fma.rn.f32x2 %0, %1, %2, %0;" : "+l"(acc) : "l"(a), "l"(b));
}
__device__ __forceinline__ float2 up2(unsigned long long v) {
    float2 r;
    asm("mov.b64 {%0, %1}, %2;" : "=f"(r.x), "=f"(r.y) : "l"(v));
    return r;
}
// ---------------- cp.async helpers ----------------
__device__ __forceinline__ void cpa16(uint32_t smem_dst, const void* gmem_src) {
    asm volatile("cp.async.cg.shared.global [%0], [%1], 16;"
                 :: "r"(smem_dst), "l"(gmem_src));
}
__device__ __forceinline__ void cpa_commit_wait() {
    asm volatile("cp.async.commit_group;");
    asm volatile("cp.async.wait_group 0;");
}

// ---------------------------------------------------------------------------
// k1: y = x @ W1. 64 nodes/block, 256 threads, 2 nodes x 4 cols per thread.
//     x staged UNTRANSPOSED via cp.async (deep MLP, no reg pressure);
//     compute reads x as broadcast LDS.64 pairs. Writes g_y AND g_agg = y.
// ---------------------------------------------------------------------------
__global__ __launch_bounds__(256) void k1_gemm_y(
    const float* __restrict__ x, const float* __restrict__ W1)
{
    __shared__ float W1s[D_FEAT * HIDDEN];       // 12 KB, row f contiguous
    __shared__ float xs[64 * XS_STRIDE];         // 25.6 KB, xs[node][f]

    const int tid = threadIdx.x;
    const int node0 = blockIdx.x * 64;
    const uint32_t xs_base  = (uint32_t)__cvta_generic_to_shared(xs);
    const uint32_t w1s_base = (uint32_t)__cvta_generic_to_shared(W1s);

    // stage W1 via cp.async (768 float4)
    {
        const float4* W14 = (const float4*)W1;
        for (int i = tid; i < D_FEAT * HIDDEN / 4; i += 256)
            cpa16(w1s_base + i * 16, &W14[i]);
    }
    // stage x via cp.async: 64 nodes x 24 float4 (OOB nodes clamped; stores guarded)
    {
        const float4* x4 = (const float4*)x;
        for (int i = tid; i < 64 * 24; i += 256) {
            const int nl = i / 24, fq = i % 24;
            int node = node0 + nl;
            if (node >= N_NODES) node = N_NODES - 1;   // clamp: data unused
            cpa16(xs_base + (nl * XS_STRIDE + fq * 4) * 4, &x4[node * 24 + fq]);
        }
    }
    if (blockIdx.x == 0) {
        for (int i = tid; i < N_GRAPHS * HIDDEN; i += 256) g_pool[i] = 0.0f;
        if (tid < N_GRAPHS) g_cnt[tid] = 0.0f;
        if (tid == 0) g_done = 0u;
    }
    cpa_commit_wait();
    __syncthreads();

    const int np = tid >> 3;   // 0..31 : node pair
    const int cq = tid & 7;    // 0..7  : col quad
    const int nA = np * 2;     // local node A
    const int nB = nA + 1;     // local node B

    unsigned long long a00 = 0ull, a01 = 0ull, a10 = 0ull, a11 = 0ull;

#pragma unroll 8
    for (int f2 = 0; f2 < D_FEAT / 2; f2++) {
        const int f = f2 * 2;
        const float2 xa = *(const float2*)&xs[nA * XS_STRIDE + f];  // node A, f/f+1
        const float2 xb = *(const float2*)&xs[nB * XS_STRIDE + f];  // node B, f/f+1
        const ulonglong2 w0 = *(const ulonglong2*)&W1s[f * HIDDEN + cq * 4];
        const ulonglong2 w1 = *(const ulonglong2*)&W1s[(f + 1) * HIDDEN + cq * 4];
        unsigned long long d;
        d = pk2(xa.x, xa.x); ffma2(a00, d, w0.x); ffma2(a01, d, w0.y);
        d = pk2(xb.x, xb.x); ffma2(a10, d, w0.x); ffma2(a11, d, w0.y);
        d = pk2(xa.y, xa.y); ffma2(a00, d, w1.x); ffma2(a01, d, w1.y);
        d = pk2(xb.y, xb.y); ffma2(a10, d, w1.x); ffma2(a11, d, w1.y);
    }

    const float2 u00 = up2(a00), u01 = up2(a01), u10 = up2(a10), u11 = up2(a11);
    const int n0 = node0 + nA;

    if (n0 < N_NODES) {
        const float4 r = make_float4(u00.x, u00.y, u01.x, u01.y);
        *(float4*)&g_y[n0 * HIDDEN + cq * 4]   = r;
        *(float4*)&g_agg[n0 * HIDDEN + cq * 4] = r;
    }
    if (n0 + 1 < N_NODES) {
        const float4 r = make_float4(u10.x, u10.y, u11.x, u11.y);
        *(float4*)&g_y[(n0 + 1) * HIDDEN + cq * 4]   = r;
        *(float4*)&g_agg[(n0 + 1) * HIDDEN + cq * 4] = r;
    }
}

// ---------------------------------------------------------------------------
// k2: edge scatter in 32-dim space; 8 lanes/edge, red.global.add.v4.f32
// ---------------------------------------------------------------------------
__global__ __launch_bounds__(256) void k2_scatter(
    const int* __restrict__ edge_index)
{
    const int t   = blockIdx.x * 256 + threadIdx.x;
    const int e   = t >> 3;
    const int sub = t & 7;
    if (e >= N_EDGES) return;

    const int s = __ldg(&edge_index[e]);            // src
    const int d = __ldg(&edge_index[N_EDGES + e]);  // dst

    const float4 v = *reinterpret_cast<const float4*>(&g_y[s * HIDDEN + sub * 4]);
    float* p = &g_agg[d * HIDDEN + sub * 4];
    asm volatile("red.global.add.v4.f32 [%0], {%1, %2, %3, %4};"
                 :: "l"(p), "f"(v.x), "f"(v.y), "f"(v.z), "f"(v.w)
                 : "memory");
}

// ---------------------------------------------------------------------------
// k3: h = relu(agg+b1) (agg already includes y); h2 = relu(h@W2+b2);
//     run-length smem pooling (batch is sorted); last-block head epilogue.
// ---------------------------------------------------------------------------
__global__ __launch_bounds__(256) void k3_mlp_pool(
    const float* __restrict__ b1, const float* __restrict__ W2,
    const float* __restrict__ b2, const int* __restrict__ batch,
    const float* __restrict__ Wc, const float* __restrict__ bc,
    float* __restrict__ out)
{
    __shared__ float W2s[HIDDEN * HIDDEN];   // 4 KB
    __shared__ float hs[32 * HS_STRIDE];     // 4.6 KB (layer-1 output)
    __shared__ float h2s[32 * HS_STRIDE];    // 4.6 KB (layer-2 output)
    __shared__ int   sb[32];                 // batch ids of this block's nodes
    __shared__ bool  amLast;

    const int tid = threadIdx.x;
    const int node0 = blockIdx.x * 32;

    {
        const float4* W24 = (const float4*)W2;
        float4* W2s4 = (float4*)W2s;
        for (int i = tid; i < HIDDEN * HIDDEN / 4; i += 256)
            W2s4[i] = W24[i];
    }
    if (tid < 32) {
        const int nd = node0 + tid;
        sb[tid] = (nd < N_NODES) ? batch[nd] : -1;
    }

    const int nl   = tid >> 3;
    const int sub  = tid & 7;
    const int node = node0 + nl;

    // h = relu(agg + b1), staged to smem
    {
        float4 h = make_float4(0.f, 0.f, 0.f, 0.f);
        if (node < N_NODES) {
            const float4 a  = *(const float4*)&g_agg[node * HIDDEN + sub * 4];
            const float4 bv = *(const float4*)&b1[sub * 4];
            h.x = fmaxf(a.x + bv.x, 0.f);
            h.y = fmaxf(a.y + bv.y, 0.f);
            h.z = fmaxf(a.z + bv.z, 0.f);
            h.w = fmaxf(a.w + bv.w, 0.f);
        }
        *(float4*)&hs[nl * HS_STRIDE + sub * 4] = h;
    }
    __syncthreads();

    // h2 = relu(h @ W2 + b2)
    float4 acc = make_float4(0.f, 0.f, 0.f, 0.f);
#pragma unroll
    for (int kq = 0; kq < 8; kq++) {
        const float4 hv = *(const float4*)&hs[nl * HS_STRIDE + kq * 4];
        {
            const float4 wv = *(const float4*)&W2s[(kq * 4 + 0) * HIDDEN + sub * 4];
            acc.x += hv.x * wv.x; acc.y += hv.x * wv.y; acc.z += hv.x * wv.z; acc.w += hv.x * wv.w;
        }
        {
            const float4 wv = *(const float4*)&W2s[(kq * 4 + 1) * HIDDEN + sub * 4];
            acc.x += hv.y * wv.x; acc.y += hv.y * wv.y; acc.z += hv.y * wv.z; acc.w += hv.y * wv.w;
        }
        {
            const float4 wv = *(const float4*)&W2s[(kq * 4 + 2) * HIDDEN + sub * 4];
            acc.x += hv.z * wv.x; acc.y += hv.z * wv.y; acc.z += hv.z * wv.z; acc.w += hv.z * wv.w;
        }
        {
            const float4 wv = *(const float4*)&W2s[(kq * 4 + 3) * HIDDEN + sub * 4];
            acc.x += hv.w * wv.x; acc.y += hv.w * wv.y; acc.z += hv.w * wv.z; acc.w += hv.w * wv.w;
        }
    }

    {
        const float4 bv = *(const float4*)&b2[sub * 4];
        acc.x = fmaxf(acc.x + bv.x, 0.f);
        acc.y = fmaxf(acc.y + bv.y, 0.f);
        acc.z = fmaxf(acc.z + bv.z, 0.f);
        acc.w = fmaxf(acc.w + bv.w, 0.f);
        *(float4*)&h2s[nl * HS_STRIDE + sub * 4] = acc;
    }
    __syncthreads();

    // run-length pooling: batch is sorted -> contiguous graph runs per block.
    if (tid < 8) {
        const int cq = tid;
        float4 pacc = make_float4(0.f, 0.f, 0.f, 0.f);
        float cnt = 0.0f;
        int curg = -1;
        for (int n = 0; n < 32; n++) {
            const int g = sb[n];
            if (g != curg) {
                if (curg >= 0) {
                    float* p = &g_pool[curg * HIDDEN + cq * 4];
                    asm volatile("red.global.add.v4.f32 [%0], {%1, %2, %3, %4};"
                                 :: "l"(p), "f"(pacc.x), "f"(pacc.y), "f"(pacc.z), "f"(pacc.w)
                                 : "memory");
                    if (cq == 0) atomicAdd(&g_cnt[curg], cnt);
                }
                curg = g;
                pacc = make_float4(0.f, 0.f, 0.f, 0.f);
                cnt = 0.0f;
            }
            if (g >= 0) {
                const float4 h = *(const float4*)&h2s[n * HS_STRIDE + cq * 4];
                pacc.x += h.x; pacc.y += h.y; pacc.z += h.z; pacc.w += h.w;
                cnt += 1.0f;
            }
        }
        if (curg >= 0) {
            float* p = &g_pool[curg * HIDDEN + cq * 4];
            asm volatile("red.global.add.v4.f32 [%0], {%1, %2, %3, %4};"
                         :: "l"(p), "f"(pacc.x), "f"(pacc.y), "f"(pacc.z), "f"(pacc.w)
                         : "memory");
            if (cq == 0) atomicAdd(&g_cnt[curg], cnt);
        }
    }

    // -------- last-block epilogue (head GEMV) --------
    __threadfence();
    __syncthreads();
    if (tid == 0)
        amLast = (atomicAdd(&g_done, 1u) == gridDim.x - 1u);
    __syncthreads();

    if (amLast) {
        __threadfence();
        const int g = tid; // 256 threads = 256 graphs
        const float inv = 1.0f / fmaxf(g_cnt[g], 1.0f);
        float o0 = 0.0f, o1 = 0.0f;
#pragma unroll
        for (int k = 0; k < HIDDEN; k++) {
            const float p = g_pool[g * HIDDEN + k] * inv;
            o0 += p * Wc[k * 2 + 0];
            o1 += p * Wc[k * 2 + 1];
        }
        out[g * 2 + 0] = o0 + bc[0];
        out[g * 2 + 1] = o1 + bc[1];
    }
}

// ---------------------------------------------------------------------------
// launch — inputs: x, edge_index, batch, W1, b1, W2, b2, Wc, bc (idx int32)
// ---------------------------------------------------------------------------
extern "C" void kernel_launch(void* const* d_in, const int* in_sizes, int n_in,
                              void* d_out, int out_size)
{
    const float* x    = (const float*)d_in[0];
    const int*   ei   = (const int*)d_in[1];
    const int*   bat  = (const int*)d_in[2];
    const float* W1   = (const float*)d_in[3];
    const float* b1   = (const float*)d_in[4];
    const float* W2   = (const float*)d_in[5];
    const float* b2   = (const float*)d_in[6];
    const float* Wc   = (const float*)d_in[7];
    const float* bc   = (const float*)d_in[8];
    float*       out  = (float*)d_out;

    k1_gemm_y<<<(N_NODES + 63) / 64, 256>>>(x, W1);
    k2_scatter<<<(N_EDGES * 8 + 255) / 256, 256>>>(ei);
    k3_mlp_pool<<<(N_NODES + 31) / 32, 256>>>(b1, W2, b2, bat, Wc, bc, out);
}